// round 9
// baseline (speedup 1.0000x reference)
#include <cuda_runtime.h>
#include <cstdint>

// Problem constants
#define NB 256     // batch
#define NN 2304    // input capsules
#define NI 8       // in_dim
#define NCLS 10    // classes
#define NCH 5      // classes per warp (c-split)
#define ND 16      // out_dim
#define NE 160     // NCLS*ND

#define NCHUNK_R 32                // n per route chunk
#define NUM_CHUNKS_R 72
#define NCHUNK_P 16                // n per produce chunk
#define NUM_CHUNKS_P 144
#define NGROUP 4

#define STAGE_N 4                   // n per cp.async stage
#define WN_F4 (NI * NE / 4)         // 320 float4 per n
#define STAGE_F4 (STAGE_N * WN_F4)  // 1280 float4 (20 KB)
#define XROW_R (NCHUNK_R * 2 + 1)   // 65 f4 per b-row (route)
#define XROW_P (NCHUNK_P * 2 + 1)   // 33 f4 per b-row (produce)

// Scratch (device globals — allocation-free kernel_launch).
__device__ float g_part[(size_t)NUM_CHUNKS_P * NB * NE];  // per-chunk partial sums
__device__ float g_part2[(size_t)NGROUP * NB * NE];       // stage-A reduced partials
__device__ float g_S[NB * NE];                            // S_acc, layout [c][b][d]

// ---- packed f32x2 helpers (sm_103a) ----
__device__ __forceinline__ uint64_t pk2(float a, float b) {
  uint64_t r; asm("mov.b64 %0,{%1,%2};" : "=l"(r) : "f"(a), "f"(b)); return r;
}
__device__ __forceinline__ uint64_t mul2(uint64_t a, uint64_t b) {
  uint64_t d; asm("mul.rn.f32x2 %0,%1,%2;" : "=l"(d) : "l"(a), "l"(b)); return d;
}
__device__ __forceinline__ void fma2(uint64_t& d, uint64_t a, uint64_t b) {
  asm("fma.rn.f32x2 %0,%1,%2,%0;" : "+l"(d) : "l"(a), "l"(b));
}
__device__ __forceinline__ float2 unpk(uint64_t v) {
  float2 r; asm("mov.b64 {%0,%1},%2;" : "=f"(r.x), "=f"(r.y) : "l"(v)); return r;
}
__device__ __forceinline__ void cpasync16(uint32_t dst, const void* src) {
  asm volatile("cp.async.ca.shared.global [%0], [%1], 16;" :: "r"(dst), "l"(src));
}
__device__ __forceinline__ void bar_pair(int wb) {
  asm volatile("bar.sync %0, 64;" :: "r"(wb + 1) : "memory");
}

// W stage: 1280 float4 by 128 threads = 10 each, coalesced.
__device__ __forceinline__ void load_w_stage(float4* sdst, const float4* gsrc) {
  const uint32_t base = (uint32_t)__cvta_generic_to_shared(sdst);
#pragma unroll
  for (int k = 0; k < STAGE_F4 / 128; k++) {
    const int idx = threadIdx.x + k * 128;
    cpasync16(base + idx * 16, gsrc + idx);
  }
}

// ---------------------------------------------------------------------------
// produce: s0 partials = Sum_n u_hat. b_t=4: warp covers 32 b (8 bq x 4 bb),
// block = ch(2) x wb(2) covering 64 b x 10 c. Grid (144, 4). 16 n per chunk.
// x read as scalar smem broadcasts (no xr register arrays).
// ---------------------------------------------------------------------------
__global__ void __launch_bounds__(128, 3)
produce_kernel(const float* __restrict__ x, const float* __restrict__ W) {
  __shared__ float4 sW[2][STAGE_F4];
  __shared__ float4 sX[64 * XROW_P];
  const int chunk = blockIdx.x;
  const int n0 = chunk * NCHUNK_P;
  const int warp = threadIdx.x >> 5;
  const int lane = threadIdx.x & 31;
  const int ch = warp & 1, wb = warp >> 1;
  const int bq = lane >> 2, q = lane & 3;
  const int c0 = ch * NCH;
  const int b_blk = blockIdx.y * 64;
  const int bl = wb * 32 + bq;     // local row base; b's = bl + 8*bb
  const float* sXf = reinterpret_cast<const float*>(sX);

  uint64_t sp2[4][NCH][2];
#pragma unroll
  for (int bb = 0; bb < 4; bb++)
#pragma unroll
    for (int c = 0; c < NCH; c++) { sp2[bb][c][0] = pk2(0.f, 0.f); sp2[bb][c][1] = pk2(0.f, 0.f); }

  // x chunk: 64 rows x 32 f4 (16 n), padded rows of 33. 2048 f4 / 128 thr = 16 each.
  {
    const int t = threadIdx.x;
    const int r = t >> 1;            // 0..63
    const int half = (t & 1) * 16;
    const float4* src = reinterpret_cast<const float4*>(x) +
                        ((size_t)(b_blk + r) * NN + n0) * 2 + half;
    const uint32_t base = (uint32_t)__cvta_generic_to_shared(sX + r * XROW_P + half);
#pragma unroll
    for (int j = 0; j < 16; j++)
      cpasync16(base + j * 16, src + j);
  }
  load_w_stage(sW[0], reinterpret_cast<const float4*>(W) + (size_t)n0 * WN_F4);
  asm volatile("cp.async.commit_group;");

#pragma unroll 1
  for (int s = 0; s < NCHUNK_P / STAGE_N; s++) {   // 4 stages
    if (s + 1 < NCHUNK_P / STAGE_N) {
      load_w_stage(sW[(s + 1) & 1],
                   reinterpret_cast<const float4*>(W) + (size_t)(n0 + (s + 1) * STAGE_N) * WN_F4);
      asm volatile("cp.async.commit_group;");
      asm volatile("cp.async.wait_group 1;");
    } else {
      asm volatile("cp.async.wait_group 0;");
    }
    __syncthreads();
    const float4* buf = sW[s & 1];
#pragma unroll
    for (int t = 0; t < STAGE_N; t++) {
      const int nn = s * STAGE_N + t;
      const float4* Wn = buf + t * WN_F4;
#pragma unroll
      for (int i = 0; i < NI; i++) {
        uint64_t x2[4];
#pragma unroll
        for (int bb = 0; bb < 4; bb++) {
          const float xv = sXf[(bl + 8 * bb) * (XROW_P * 4) + nn * 8 + i];
          x2[bb] = pk2(xv, xv);
        }
#pragma unroll
        for (int c = 0; c < NCH; c++) {
          const ulonglong2 w = *reinterpret_cast<const ulonglong2*>(Wn + i * 40 + (c0 + c) * 4 + q);
#pragma unroll
          for (int bb = 0; bb < 4; bb++) {
            fma2(sp2[bb][c][0], x2[bb], w.x);
            fma2(sp2[bb][c][1], x2[bb], w.y);
          }
        }
      }
    }
    __syncthreads();
  }
  float* pp = g_part + (size_t)chunk * (NB * NE);
#pragma unroll
  for (int bb = 0; bb < 4; bb++) {
    const int b = b_blk + bl + 8 * bb;
#pragma unroll
    for (int c = 0; c < NCH; c++) {
      ulonglong2 v; v.x = sp2[bb][c][0]; v.y = sp2[bb][c][1];
      *reinterpret_cast<ulonglong2*>(pp + ((size_t)(c0 + c) * NB + b) * ND + q * 4) = v;
    }
  }
}

// ---------------------------------------------------------------------------
// Routing pass: b_t=2, c-split softmax across warp pairs, 32 n per chunk.
// Grid (72, 8). x as scalar smem broadcasts.
// ---------------------------------------------------------------------------
__global__ void __launch_bounds__(128, 3)
route_kernel(const float* __restrict__ x, const float* __restrict__ W) {
  __shared__ float4 sW[2][STAGE_F4];
  __shared__ float4 sX[32 * XROW_R];
  __shared__ float4 sEx[2][2][2][8];   // [parity][wb][ch][bq]
  const int chunk = blockIdx.x;
  const int n0 = chunk * NCHUNK_R;
  const int warp = threadIdx.x >> 5;
  const int lane = threadIdx.x & 31;
  const int ch = warp & 1, wb = warp >> 1;
  const int bq = lane >> 2, q = lane & 3;
  const int c0 = ch * NCH;
  const int b_blk = blockIdx.y * 32;
  const int bl0 = wb * 16 + bq, bl1 = bl0 + 8;
  const int b0 = b_blk + bl0, b1 = b_blk + bl1;
  const float* sXf = reinterpret_cast<const float*>(sX);

  uint64_t S2[2][NCH][2];
#pragma unroll
  for (int bb = 0; bb < 2; bb++) {
    const int b = bb ? b1 : b0;
#pragma unroll
    for (int c = 0; c < NCH; c++) {
      const ulonglong2 v = *reinterpret_cast<const ulonglong2*>(
          g_S + ((size_t)(c0 + c) * NB + b) * ND + q * 4);
      S2[bb][c][0] = v.x; S2[bb][c][1] = v.y;
    }
  }
  uint64_t sp2[2][NCH][2];
#pragma unroll
  for (int bb = 0; bb < 2; bb++)
#pragma unroll
    for (int c = 0; c < NCH; c++) { sp2[bb][c][0] = pk2(0.f, 0.f); sp2[bb][c][1] = pk2(0.f, 0.f); }

  // x chunk: 32 rows x 64 f4 (32 n), padded 65. 2048 f4 / 128 thr = 16 each.
  {
    const int t = threadIdx.x;
    const int r = t >> 2;
    const int j0 = (t & 3) * 16;
    const float4* src = reinterpret_cast<const float4*>(x) +
                        ((size_t)(b_blk + r) * NN + n0) * 2 + j0;
    const uint32_t base = (uint32_t)__cvta_generic_to_shared(sX + r * XROW_R + j0);
#pragma unroll
    for (int j = 0; j < 16; j++)
      cpasync16(base + j * 16, src + j);
  }
  load_w_stage(sW[0], reinterpret_cast<const float4*>(W) + (size_t)n0 * WN_F4);
  asm volatile("cp.async.commit_group;");

#pragma unroll 1
  for (int s = 0; s < NCHUNK_R / STAGE_N; s++) {   // 8 stages
    if (s + 1 < NCHUNK_R / STAGE_N) {
      load_w_stage(sW[(s + 1) & 1],
                   reinterpret_cast<const float4*>(W) + (size_t)(n0 + (s + 1) * STAGE_N) * WN_F4);
      asm volatile("cp.async.commit_group;");
      asm volatile("cp.async.wait_group 1;");
    } else {
      asm volatile("cp.async.wait_group 0;");
    }
    __syncthreads();
    const float4* buf = sW[s & 1];
#pragma unroll
    for (int t = 0; t < STAGE_N; t++) {
      const int nn = s * STAGE_N + t;
      const int par = nn & 1;
      const float4* Wn = buf + t * WN_F4;

      uint64_t u2[2][NCH][2];
#pragma unroll
      for (int i = 0; i < NI; i++) {
        const float xv0 = sXf[bl0 * (XROW_R * 4) + nn * 8 + i];
        const float xv1 = sXf[bl1 * (XROW_R * 4) + nn * 8 + i];
        const uint64_t x20 = pk2(xv0, xv0);
        const uint64_t x21 = pk2(xv1, xv1);
#pragma unroll
        for (int c = 0; c < NCH; c++) {
          const ulonglong2 w = *reinterpret_cast<const ulonglong2*>(Wn + i * 40 + (c0 + c) * 4 + q);
          if (i == 0) {
            u2[0][c][0] = mul2(x20, w.x); u2[0][c][1] = mul2(x20, w.y);
            u2[1][c][0] = mul2(x21, w.x); u2[1][c][1] = mul2(x21, w.y);
          } else {
            fma2(u2[0][c][0], x20, w.x); fma2(u2[0][c][1], x20, w.y);
            fma2(u2[1][c][0], x21, w.x); fma2(u2[1][c][1], x21, w.y);
          }
        }
      }
      float lg[2][NCH];
#pragma unroll
      for (int bb = 0; bb < 2; bb++)
#pragma unroll
        for (int c = 0; c < NCH; c++) {
          uint64_t tt = mul2(u2[bb][c][0], S2[bb][c][0]);
          fma2(tt, u2[bb][c][1], S2[bb][c][1]);
          const float2 f = unpk(tt);
          float v = f.x + f.y;
          v += __shfl_xor_sync(0xffffffffu, v, 1);
          v += __shfl_xor_sync(0xffffffffu, v, 2);
          lg[bb][c] = v;
        }
      float m[2], sm[2];
#pragma unroll
      for (int bb = 0; bb < 2; bb++) {
        float mm = lg[bb][0];
#pragma unroll
        for (int c = 1; c < NCH; c++) mm = fmaxf(mm, lg[bb][c]);
        float ss = 0.f;
#pragma unroll
        for (int c = 0; c < NCH; c++) { lg[bb][c] = __expf(lg[bb][c] - mm); ss += lg[bb][c]; }
        m[bb] = mm; sm[bb] = ss;
      }
      if (q == 0) sEx[par][wb][ch][bq] = make_float4(m[0], sm[0], m[1], sm[1]);
      bar_pair(wb);
      const float4 o = sEx[par][wb][ch ^ 1][bq];
      const float mo[2] = {o.x, o.z};
      const float so[2] = {o.y, o.w};
#pragma unroll
      for (int bb = 0; bb < 2; bb++) {
        const float M = fmaxf(m[bb], mo[bb]);
        const float am = __expf(m[bb] - M);
        const float ao = __expf(mo[bb] - M);
        const float fac = am * __frcp_rn(sm[bb] * am + so[bb] * ao);
#pragma unroll
        for (int c = 0; c < NCH; c++) {
          const float p = lg[bb][c] * fac;
          const uint64_t p2 = pk2(p, p);
          fma2(sp2[bb][c][0], p2, u2[bb][c][0]);
          fma2(sp2[bb][c][1], p2, u2[bb][c][1]);
        }
      }
    }
    __syncthreads();
  }
  float* pp = g_part + (size_t)chunk * (NB * NE);
#pragma unroll
  for (int bb = 0; bb < 2; bb++) {
    const int b = bb ? b1 : b0;
#pragma unroll
    for (int c = 0; c < NCH; c++) {
      ulonglong2 v; v.x = sp2[bb][c][0]; v.y = sp2[bb][c][1];
      *reinterpret_cast<ulonglong2*>(pp + ((size_t)(c0 + c) * NB + b) * ND + q * 4) = v;
    }
  }
}

// ---------------------------------------------------------------------------
// Reduction stage A: nchunks -> 4 group partials. Grid (160, 4).
// ---------------------------------------------------------------------------
__global__ void reduceA_kernel(int nchunks) {
  const int t = blockIdx.x * blockDim.x + threadIdx.x;
  const int g = blockIdx.y;
  const int per = nchunks >> 2;
  float sum = 0.f;
  const int k0 = g * per;
#pragma unroll 6
  for (int k = k0; k < k0 + per; k++)
    sum += g_part[(size_t)k * (NB * NE) + t];
  g_part2[(size_t)g * (NB * NE) + t] = sum;
}

// Reduction stage B: 4 -> 1 + bias + S_acc update / final squash.
__global__ void reduceB_kernel(int mode, float* __restrict__ out) {
  const int t = blockIdx.x * blockDim.x + threadIdx.x;
  float sum = 0.f;
#pragma unroll
  for (int g = 0; g < NGROUP; g++) sum += g_part2[(size_t)g * (NB * NE) + t];

  if (mode == 0) {
    g_S[t] = 0.1f * sum + 0.1f;
  } else if (mode == 1) {
    g_S[t] = g_S[t] + sum + 0.1f;
  } else {
    const float s = sum + 0.1f;
    float nsq = s * s;
    nsq += __shfl_xor_sync(0xffffffffu, nsq, 1);
    nsq += __shfl_xor_sync(0xffffffffu, nsq, 2);
    nsq += __shfl_xor_sync(0xffffffffu, nsq, 4);
    nsq += __shfl_xor_sync(0xffffffffu, nsq, 8);
    const float nrm = sqrtf(nsq);
    const float v = s * nrm / (1.f + nsq);
    const int d = t & 15;
    const int b = (t >> 4) & 255;
    const int c = t >> 12;
    out[((size_t)b * NCLS + c) * ND + d] = v;
  }
}

extern "C" void kernel_launch(void* const* d_in, const int* in_sizes, int n_in,
                              void* d_out, int out_size) {
  const float* x = (const float*)d_in[0];   // [256, 2304, 8] f32
  const float* W = (const float*)d_in[1];   // [2304, 8, 160] f32
  float* out = (float*)d_out;               // [256, 10, 16] f32

  const dim3 pgrid(NUM_CHUNKS_P, 4);        // produce: 64 b per block
  const dim3 rgrid(NUM_CHUNKS_R, 8);        // route: 32 b per block
  const dim3 rgridA(160, NGROUP);

  produce_kernel<<<pgrid, 128>>>(x, W);
  reduceA_kernel<<<rgridA, 256>>>(NUM_CHUNKS_P);
  reduceB_kernel<<<160, 256>>>(0, out);    // g_S = s0
  route_kernel<<<rgrid, 128>>>(x, W);
  reduceA_kernel<<<rgridA, 256>>>(NUM_CHUNKS_R);
  reduceB_kernel<<<160, 256>>>(1, out);    // g_S = s0 + s1
  route_kernel<<<rgrid, 128>>>(x, W);
  reduceA_kernel<<<rgridA, 256>>>(NUM_CHUNKS_R);
  reduceB_kernel<<<160, 256>>>(2, out);    // final + squash
}

// round 10
// speedup vs baseline: 1.8051x; 1.8051x over previous
#include <cuda_runtime.h>
#include <cstdint>

// Problem constants
#define NB 256     // batch
#define NN 2304    // input capsules
#define NI 8       // in_dim
#define NCLS 10    // classes
#define NCH 5      // classes per half (c-split)
#define ND 16      // out_dim
#define NE 160     // NCLS*ND

#define NCHUNK_R 16                // n per route chunk
#define NUM_CHUNKS_R 144
#define NCHUNK_P 8                 // n per produce chunk
#define NUM_CHUNKS_P 288
#define NGROUP 4

#define STAGE_N 4                   // n per cp.async stage (both kernels)
#define WN_F4 (NI * NE / 4)         // 320 float4 per n
#define STAGE_F4 (STAGE_N * WN_F4)  // 1280 float4 (20 KB)
#define XROW_R 33                   // route: 32 data f4 + 1 pad
#define XROW_P 17                   // produce: 16 data f4 + 1 pad

// Scratch (device globals — allocation-free kernel_launch).
__device__ float g_part[(size_t)NUM_CHUNKS_P * NB * NE];  // per-chunk partial sums
__device__ float g_part2[(size_t)NGROUP * NB * NE];       // stage-A reduced partials
__device__ float g_S[NB * NE];                            // S_acc, layout [c][b][d]

// ---- packed f32x2 helpers (sm_103a) ----
__device__ __forceinline__ uint64_t pk2(float a, float b) {
  uint64_t r; asm("mov.b64 %0,{%1,%2};" : "=l"(r) : "f"(a), "f"(b)); return r;
}
__device__ __forceinline__ uint64_t mul2(uint64_t a, uint64_t b) {
  uint64_t d; asm("mul.rn.f32x2 %0,%1,%2;" : "=l"(d) : "l"(a), "l"(b)); return d;
}
__device__ __forceinline__ void fma2(uint64_t& d, uint64_t a, uint64_t b) {
  asm("fma.rn.f32x2 %0,%1,%2,%0;" : "+l"(d) : "l"(a), "l"(b));
}
__device__ __forceinline__ float2 unpk(uint64_t v) {
  float2 r; asm("mov.b64 {%0,%1},%2;" : "=f"(r.x), "=f"(r.y) : "l"(v)); return r;
}
__device__ __forceinline__ void cpasync16(uint32_t dst, const void* src) {
  asm volatile("cp.async.ca.shared.global [%0], [%1], 16;" :: "r"(dst), "l"(src));
}

// W stage: 1280 float4 by 128 threads = 10 each, coalesced.
__device__ __forceinline__ void load_w_stage(float4* sdst, const float4* gsrc) {
  const uint32_t base = (uint32_t)__cvta_generic_to_shared(sdst);
#pragma unroll
  for (int k = 0; k < STAGE_F4 / 128; k++) {
    const int idx = threadIdx.x + k * 128;
    cpasync16(base + idx * 16, gsrc + idx);
  }
}

// ---------------------------------------------------------------------------
// produce: s0 partials = Sum_n u_hat. b_t=4: warp covers 32 b (8 bq x 4 bb),
// block = ch(2) x wb(2) covering 64 b x 10 c. Grid (288, 4). 8 n per chunk.
// (exact round-7 structure — measured best)
// ---------------------------------------------------------------------------
__global__ void __launch_bounds__(128, 3)
produce_kernel(const float* __restrict__ x, const float* __restrict__ W) {
  __shared__ float4 sW[2][STAGE_F4];
  __shared__ float4 sX[64 * XROW_P];
  const int chunk = blockIdx.x;
  const int n0 = chunk * NCHUNK_P;
  const int warp = threadIdx.x >> 5;
  const int lane = threadIdx.x & 31;
  const int ch = warp & 1, wb = warp >> 1;
  const int bq = lane >> 2, q = lane & 3;
  const int c0 = ch * NCH;
  const int b_blk = blockIdx.y * 64;
  const int bl = wb * 32 + bq;     // local row base; b's = bl + 8*bb

  uint64_t sp2[4][NCH][2];
#pragma unroll
  for (int bb = 0; bb < 4; bb++)
#pragma unroll
    for (int c = 0; c < NCH; c++) { sp2[bb][c][0] = pk2(0.f, 0.f); sp2[bb][c][1] = pk2(0.f, 0.f); }

  // x chunk: 64 rows x 16 f4 (8 n), padded rows of 17. 1024 f4 / 128 thr = 8 each.
  {
    const int t = threadIdx.x;
    const int r = t >> 1;            // 0..63
    const int half = t & 1;
    const float4* src = reinterpret_cast<const float4*>(x) +
                        ((size_t)(b_blk + r) * NN + n0) * 2 + half * 8;
    const uint32_t base = (uint32_t)__cvta_generic_to_shared(sX + r * XROW_P + half * 8);
#pragma unroll
    for (int j = 0; j < 8; j++)
      cpasync16(base + j * 16, src + j);
  }
  load_w_stage(sW[0], reinterpret_cast<const float4*>(W) + (size_t)n0 * WN_F4);
  asm volatile("cp.async.commit_group;");

#pragma unroll
  for (int s = 0; s < NCHUNK_P / STAGE_N; s++) {   // 2 stages
    if (s + 1 < NCHUNK_P / STAGE_N) {
      load_w_stage(sW[(s + 1) & 1],
                   reinterpret_cast<const float4*>(W) + (size_t)(n0 + (s + 1) * STAGE_N) * WN_F4);
      asm volatile("cp.async.commit_group;");
      asm volatile("cp.async.wait_group 1;");
    } else {
      asm volatile("cp.async.wait_group 0;");
    }
    __syncthreads();
    const float4* buf = sW[s & 1];
#pragma unroll
    for (int t = 0; t < STAGE_N; t++) {
      const int nn = s * STAGE_N + t;
      float xr[4][NI];
#pragma unroll
      for (int bb = 0; bb < 4; bb++) {
        const float4 xa = sX[(bl + 8 * bb) * XROW_P + nn * 2];
        const float4 xb = sX[(bl + 8 * bb) * XROW_P + nn * 2 + 1];
        xr[bb][0] = xa.x; xr[bb][1] = xa.y; xr[bb][2] = xa.z; xr[bb][3] = xa.w;
        xr[bb][4] = xb.x; xr[bb][5] = xb.y; xr[bb][6] = xb.z; xr[bb][7] = xb.w;
      }
      const float4* Wn = buf + t * WN_F4;
#pragma unroll
      for (int i = 0; i < NI; i++) {
        uint64_t x2[4];
#pragma unroll
        for (int bb = 0; bb < 4; bb++) x2[bb] = pk2(xr[bb][i], xr[bb][i]);
#pragma unroll
        for (int c = 0; c < NCH; c++) {
          const ulonglong2 w = *reinterpret_cast<const ulonglong2*>(Wn + i * 40 + (c0 + c) * 4 + q);
#pragma unroll
          for (int bb = 0; bb < 4; bb++) {
            fma2(sp2[bb][c][0], x2[bb], w.x);
            fma2(sp2[bb][c][1], x2[bb], w.y);
          }
        }
      }
    }
    __syncthreads();
  }
  float* pp = g_part + (size_t)chunk * (NB * NE);
#pragma unroll
  for (int bb = 0; bb < 4; bb++) {
    const int b = b_blk + bl + 8 * bb;
#pragma unroll
    for (int c = 0; c < NCH; c++) {
      ulonglong2 v; v.x = sp2[bb][c][0]; v.y = sp2[bb][c][1];
      *reinterpret_cast<ulonglong2*>(pp + ((size_t)(c0 + c) * NB + b) * ND + q * 4) = v;
    }
  }
}

// ---------------------------------------------------------------------------
// Routing pass: b_t=2, IN-WARP c-split. lane = half<<4 | bq<<2 | q.
// Warp covers 8 b (4 bq x 2 bt) x both c-halves x q-quarters; block = 4 warps
// = 32 b. Softmax (max,expsum) exchange via shfl.xor(16) — no barrier, no smem
// exchange, warps fully decoupled. Grid (144, 8). Otherwise round-7 identical.
// ---------------------------------------------------------------------------
__global__ void __launch_bounds__(128, 3)
route_kernel(const float* __restrict__ x, const float* __restrict__ W) {
  __shared__ float4 sW[2][STAGE_F4];
  __shared__ float4 sX[32 * XROW_R];
  const int chunk = blockIdx.x;
  const int n0 = chunk * NCHUNK_R;
  const int warp = threadIdx.x >> 5;
  const int lane = threadIdx.x & 31;
  const int half = lane >> 4;            // c-half
  const int bq = (lane >> 2) & 3;        // 0..3
  const int q  = lane & 3;               // d-quarter
  const int c0 = half * NCH;
  const int b_blk = blockIdx.y * 32;
  const int bl0 = warp * 8 + bq, bl1 = bl0 + 4;
  const int b0 = b_blk + bl0, b1 = b_blk + bl1;

  uint64_t S2[2][NCH][2];
#pragma unroll
  for (int bb = 0; bb < 2; bb++) {
    const int b = bb ? b1 : b0;
#pragma unroll
    for (int c = 0; c < NCH; c++) {
      const ulonglong2 v = *reinterpret_cast<const ulonglong2*>(
          g_S + ((size_t)(c0 + c) * NB + b) * ND + q * 4);
      S2[bb][c][0] = v.x; S2[bb][c][1] = v.y;
    }
  }
  uint64_t sp2[2][NCH][2];
#pragma unroll
  for (int bb = 0; bb < 2; bb++)
#pragma unroll
    for (int c = 0; c < NCH; c++) { sp2[bb][c][0] = pk2(0.f, 0.f); sp2[bb][c][1] = pk2(0.f, 0.f); }

  // x chunk: 32 rows x 32 f4 (16 n), padded 33. (round-7 staging)
  {
    const int t = threadIdx.x;
    const int r = t >> 2;
    const int j0 = (t & 3) * 8;
    const float4* src = reinterpret_cast<const float4*>(x) +
                        ((size_t)(b_blk + r) * NN + n0) * 2;
    const uint32_t base = (uint32_t)__cvta_generic_to_shared(sX + r * XROW_R);
#pragma unroll
    for (int j = 0; j < 8; j++)
      cpasync16(base + (j0 + j) * 16, src + j0 + j);
  }
  load_w_stage(sW[0], reinterpret_cast<const float4*>(W) + (size_t)n0 * WN_F4);
  asm volatile("cp.async.commit_group;");

#pragma unroll 1
  for (int s = 0; s < NCHUNK_R / STAGE_N; s++) {   // 4 stages
    if (s + 1 < NCHUNK_R / STAGE_N) {
      load_w_stage(sW[(s + 1) & 1],
                   reinterpret_cast<const float4*>(W) + (size_t)(n0 + (s + 1) * STAGE_N) * WN_F4);
      asm volatile("cp.async.commit_group;");
      asm volatile("cp.async.wait_group 1;");
    } else {
      asm volatile("cp.async.wait_group 0;");
    }
    __syncthreads();
    const float4* buf = sW[s & 1];
#pragma unroll
    for (int t = 0; t < STAGE_N; t++) {
      const int nn = s * STAGE_N + t;
      const float4 xa0 = sX[bl0 * XROW_R + nn * 2], xb0 = sX[bl0 * XROW_R + nn * 2 + 1];
      const float4 xa1 = sX[bl1 * XROW_R + nn * 2], xb1 = sX[bl1 * XROW_R + nn * 2 + 1];
      const float xr0[NI] = {xa0.x, xa0.y, xa0.z, xa0.w, xb0.x, xb0.y, xb0.z, xb0.w};
      const float xr1[NI] = {xa1.x, xa1.y, xa1.z, xa1.w, xb1.x, xb1.y, xb1.z, xb1.w};
      const float4* Wn = buf + t * WN_F4;

      uint64_t u2[2][NCH][2];
#pragma unroll
      for (int i = 0; i < NI; i++) {
        const uint64_t x20 = pk2(xr0[i], xr0[i]);
        const uint64_t x21 = pk2(xr1[i], xr1[i]);
#pragma unroll
        for (int c = 0; c < NCH; c++) {
          const ulonglong2 w = *reinterpret_cast<const ulonglong2*>(Wn + i * 40 + (c0 + c) * 4 + q);
          if (i == 0) {
            u2[0][c][0] = mul2(x20, w.x); u2[0][c][1] = mul2(x20, w.y);
            u2[1][c][0] = mul2(x21, w.x); u2[1][c][1] = mul2(x21, w.y);
          } else {
            fma2(u2[0][c][0], x20, w.x); fma2(u2[0][c][1], x20, w.y);
            fma2(u2[1][c][0], x21, w.x); fma2(u2[1][c][1], x21, w.y);
          }
        }
      }
      // logits: packed dot + cross-half add + q-lane reduction (lanes 0-1 bits)
      float lg[2][NCH];
#pragma unroll
      for (int bb = 0; bb < 2; bb++)
#pragma unroll
        for (int c = 0; c < NCH; c++) {
          uint64_t tt = mul2(u2[bb][c][0], S2[bb][c][0]);
          fma2(tt, u2[bb][c][1], S2[bb][c][1]);
          const float2 f = unpk(tt);
          float v = f.x + f.y;
          v += __shfl_xor_sync(0xffffffffu, v, 1);
          v += __shfl_xor_sync(0xffffffffu, v, 2);
          lg[bb][c] = v;
        }
      // local softmax half: max + exps + sum
      float m[2], sm[2];
#pragma unroll
      for (int bb = 0; bb < 2; bb++) {
        float mm = lg[bb][0];
#pragma unroll
        for (int c = 1; c < NCH; c++) mm = fmaxf(mm, lg[bb][c]);
        float ss = 0.f;
#pragma unroll
        for (int c = 0; c < NCH; c++) { lg[bb][c] = __expf(lg[bb][c] - mm); ss += lg[bb][c]; }
        m[bb] = mm; sm[bb] = ss;
      }
      // exchange (max, expsum) with the other c-half: same warp, xor lane 16
      const float mo0 = __shfl_xor_sync(0xffffffffu, m[0], 16);
      const float so0 = __shfl_xor_sync(0xffffffffu, sm[0], 16);
      const float mo1 = __shfl_xor_sync(0xffffffffu, m[1], 16);
      const float so1 = __shfl_xor_sync(0xffffffffu, sm[1], 16);
      const float mo[2] = {mo0, mo1};
      const float so[2] = {so0, so1};
#pragma unroll
      for (int bb = 0; bb < 2; bb++) {
        const float M = fmaxf(m[bb], mo[bb]);
        const float am = __expf(m[bb] - M);
        const float ao = __expf(mo[bb] - M);
        const float fac = am * __frcp_rn(sm[bb] * am + so[bb] * ao);
#pragma unroll
        for (int c = 0; c < NCH; c++) {
          const float p = lg[bb][c] * fac;
          const uint64_t p2 = pk2(p, p);
          fma2(sp2[bb][c][0], p2, u2[bb][c][0]);
          fma2(sp2[bb][c][1], p2, u2[bb][c][1]);
        }
      }
    }
    __syncthreads();
  }
  float* pp = g_part + (size_t)chunk * (NB * NE);
#pragma unroll
  for (int bb = 0; bb < 2; bb++) {
    const int b = bb ? b1 : b0;
#pragma unroll
    for (int c = 0; c < NCH; c++) {
      ulonglong2 v; v.x = sp2[bb][c][0]; v.y = sp2[bb][c][1];
      *reinterpret_cast<ulonglong2*>(pp + ((size_t)(c0 + c) * NB + b) * ND + q * 4) = v;
    }
  }
}

// ---------------------------------------------------------------------------
// Reduction stage A: nchunks -> 4 group partials. Grid (160, 4).
// ---------------------------------------------------------------------------
__global__ void reduceA_kernel(int nchunks) {
  const int t = blockIdx.x * blockDim.x + threadIdx.x;
  const int g = blockIdx.y;
  const int per = nchunks >> 2;
  float sum = 0.f;
  const int k0 = g * per;
#pragma unroll 4
  for (int k = k0; k < k0 + per; k++)
    sum += g_part[(size_t)k * (NB * NE) + t];
  g_part2[(size_t)g * (NB * NE) + t] = sum;
}

// Reduction stage B: 4 -> 1 + bias + S_acc update / final squash.
__global__ void reduceB_kernel(int mode, float* __restrict__ out) {
  const int t = blockIdx.x * blockDim.x + threadIdx.x;
  float sum = 0.f;
#pragma unroll
  for (int g = 0; g < NGROUP; g++) sum += g_part2[(size_t)g * (NB * NE) + t];

  if (mode == 0) {
    g_S[t] = 0.1f * sum + 0.1f;
  } else if (mode == 1) {
    g_S[t] = g_S[t] + sum + 0.1f;
  } else {
    const float s = sum + 0.1f;
    float nsq = s * s;
    nsq += __shfl_xor_sync(0xffffffffu, nsq, 1);
    nsq += __shfl_xor_sync(0xffffffffu, nsq, 2);
    nsq += __shfl_xor_sync(0xffffffffu, nsq, 4);
    nsq += __shfl_xor_sync(0xffffffffu, nsq, 8);
    const float nrm = sqrtf(nsq);
    const float v = s * nrm / (1.f + nsq);
    const int d = t & 15;
    const int b = (t >> 4) & 255;
    const int c = t >> 12;
    out[((size_t)b * NCLS + c) * ND + d] = v;
  }
}

extern "C" void kernel_launch(void* const* d_in, const int* in_sizes, int n_in,
                              void* d_out, int out_size) {
  const float* x = (const float*)d_in[0];   // [256, 2304, 8] f32
  const float* W = (const float*)d_in[1];   // [2304, 8, 160] f32
  float* out = (float*)d_out;               // [256, 10, 16] f32

  const dim3 pgrid(NUM_CHUNKS_P, 4);        // produce: 64 b per block
  const dim3 rgrid(NUM_CHUNKS_R, 8);        // route: 32 b per block
  const dim3 rgridA(160, NGROUP);

  produce_kernel<<<pgrid, 128>>>(x, W);
  reduceA_kernel<<<rgridA, 256>>>(NUM_CHUNKS_P);
  reduceB_kernel<<<160, 256>>>(0, out);    // g_S = s0
  route_kernel<<<rgrid, 128>>>(x, W);
  reduceA_kernel<<<rgridA, 256>>>(NUM_CHUNKS_R);
  reduceB_kernel<<<160, 256>>>(1, out);    // g_S = s0 + s1
  route_kernel<<<rgrid, 128>>>(x, W);
  reduceA_kernel<<<rgridA, 256>>>(NUM_CHUNKS_R);
  reduceB_kernel<<<160, 256>>>(2, out);    // final + squash
}

// round 13
// speedup vs baseline: 1.8876x; 1.0457x over previous
#include <cuda_runtime.h>
#include <cstdint>

// Problem constants
#define NB 256     // batch
#define NN 2304    // input capsules
#define NI 8       // in_dim
#define NCLS 10    // classes
#define NCH 5      // classes per half (c-split)
#define ND 16      // out_dim
#define NE 160     // NCLS*ND

#define NCHUNK_R 16                // n per route chunk
#define NUM_CHUNKS_R 144
#define NCHUNK_P 8                 // n per produce chunk
#define NUM_CHUNKS_P 288
#define NGROUP 4

#define STAGE_N 4                   // n per cp.async stage (both kernels)
#define WN_F4 (NI * NE / 4)         // 320 float4 per n
#define STAGE_F4 (STAGE_N * WN_F4)  // 1280 float4 (20 KB)
#define XROW_R 33                   // route: 32 data f4 + 1 pad
#define XROW_P 17                   // produce: 16 data f4 + 1 pad

// Scratch (device globals — allocation-free kernel_launch).
__device__ float g_part[(size_t)NUM_CHUNKS_P * NB * NE];  // per-chunk partial sums
__device__ float g_part2[(size_t)NGROUP * NB * NE];       // stage-A reduced partials
__device__ float g_S[NB * NE];                            // S_acc, layout [c][b][d]

// ---- packed f32x2 helpers (sm_103a) ----
__device__ __forceinline__ uint64_t pk2(float a, float b) {
  uint64_t r; asm("mov.b64 %0,{%1,%2};" : "=l"(r) : "f"(a), "f"(b)); return r;
}
__device__ __forceinline__ uint64_t mul2(uint64_t a, uint64_t b) {
  uint64_t d; asm("mul.rn.f32x2 %0,%1,%2;" : "=l"(d) : "l"(a), "l"(b)); return d;
}
__device__ __forceinline__ void fma2(uint64_t& d, uint64_t a, uint64_t b) {
  asm("fma.rn.f32x2 %0,%1,%2,%0;" : "+l"(d) : "l"(a), "l"(b));
}
__device__ __forceinline__ float2 unpk(uint64_t v) {
  float2 r; asm("mov.b64 {%0,%1},%2;" : "=f"(r.x), "=f"(r.y) : "l"(v)); return r;
}
__device__ __forceinline__ void cpasync16(uint32_t dst, const void* src) {
  asm volatile("cp.async.ca.shared.global [%0], [%1], 16;" :: "r"(dst), "l"(src));
}

// W stage: 1280 float4 by 128 threads = 10 each, coalesced.
__device__ __forceinline__ void load_w_stage(float4* sdst, const float4* gsrc) {
  const uint32_t base = (uint32_t)__cvta_generic_to_shared(sdst);
#pragma unroll
  for (int k = 0; k < STAGE_F4 / 128; k++) {
    const int idx = threadIdx.x + k * 128;
    cpasync16(base + idx * 16, gsrc + idx);
  }
}

// ---------------------------------------------------------------------------
// produce: s0 partials = Sum_n u_hat. b_t=4: warp covers 32 b (8 bq x 4 bb),
// block = ch(2) x wb(2) covering 64 b x 10 c. Grid (288, 4). 8 n per chunk.
// (measured-best structure — unchanged)
// ---------------------------------------------------------------------------
__global__ void __launch_bounds__(128, 3)
produce_kernel(const float* __restrict__ x, const float* __restrict__ W) {
  __shared__ float4 sW[2][STAGE_F4];
  __shared__ float4 sX[64 * XROW_P];
  const int chunk = blockIdx.x;
  const int n0 = chunk * NCHUNK_P;
  const int warp = threadIdx.x >> 5;
  const int lane = threadIdx.x & 31;
  const int ch = warp & 1, wb = warp >> 1;
  const int bq = lane >> 2, q = lane & 3;
  const int c0 = ch * NCH;
  const int b_blk = blockIdx.y * 64;
  const int bl = wb * 32 + bq;     // local row base; b's = bl + 8*bb

  uint64_t sp2[4][NCH][2];
#pragma unroll
  for (int bb = 0; bb < 4; bb++)
#pragma unroll
    for (int c = 0; c < NCH; c++) { sp2[bb][c][0] = pk2(0.f, 0.f); sp2[bb][c][1] = pk2(0.f, 0.f); }

  // x chunk: 64 rows x 16 f4 (8 n), padded rows of 17. 1024 f4 / 128 thr = 8 each.
  {
    const int t = threadIdx.x;
    const int r = t >> 1;            // 0..63
    const int half = t & 1;
    const float4* src = reinterpret_cast<const float4*>(x) +
                        ((size_t)(b_blk + r) * NN + n0) * 2 + half * 8;
    const uint32_t base = (uint32_t)__cvta_generic_to_shared(sX + r * XROW_P + half * 8);
#pragma unroll
    for (int j = 0; j < 8; j++)
      cpasync16(base + j * 16, src + j);
  }
  load_w_stage(sW[0], reinterpret_cast<const float4*>(W) + (size_t)n0 * WN_F4);
  asm volatile("cp.async.commit_group;");

#pragma unroll
  for (int s = 0; s < NCHUNK_P / STAGE_N; s++) {   // 2 stages
    if (s + 1 < NCHUNK_P / STAGE_N) {
      load_w_stage(sW[(s + 1) & 1],
                   reinterpret_cast<const float4*>(W) + (size_t)(n0 + (s + 1) * STAGE_N) * WN_F4);
      asm volatile("cp.async.commit_group;");
      asm volatile("cp.async.wait_group 1;");
    } else {
      asm volatile("cp.async.wait_group 0;");
    }
    __syncthreads();
    const float4* buf = sW[s & 1];
#pragma unroll
    for (int t = 0; t < STAGE_N; t++) {
      const int nn = s * STAGE_N + t;
      float xr[4][NI];
#pragma unroll
      for (int bb = 0; bb < 4; bb++) {
        const float4 xa = sX[(bl + 8 * bb) * XROW_P + nn * 2];
        const float4 xb = sX[(bl + 8 * bb) * XROW_P + nn * 2 + 1];
        xr[bb][0] = xa.x; xr[bb][1] = xa.y; xr[bb][2] = xa.z; xr[bb][3] = xa.w;
        xr[bb][4] = xb.x; xr[bb][5] = xb.y; xr[bb][6] = xb.z; xr[bb][7] = xb.w;
      }
      const float4* Wn = buf + t * WN_F4;
#pragma unroll
      for (int i = 0; i < NI; i++) {
        uint64_t x2[4];
#pragma unroll
        for (int bb = 0; bb < 4; bb++) x2[bb] = pk2(xr[bb][i], xr[bb][i]);
#pragma unroll
        for (int c = 0; c < NCH; c++) {
          const ulonglong2 w = *reinterpret_cast<const ulonglong2*>(Wn + i * 40 + (c0 + c) * 4 + q);
#pragma unroll
          for (int bb = 0; bb < 4; bb++) {
            fma2(sp2[bb][c][0], x2[bb], w.x);
            fma2(sp2[bb][c][1], x2[bb], w.y);
          }
        }
      }
    }
    __syncthreads();
  }
  float* pp = g_part + (size_t)chunk * (NB * NE);
#pragma unroll
  for (int bb = 0; bb < 4; bb++) {
    const int b = b_blk + bl + 8 * bb;
#pragma unroll
    for (int c = 0; c < NCH; c++) {
      ulonglong2 v; v.x = sp2[bb][c][0]; v.y = sp2[bb][c][1];
      *reinterpret_cast<ulonglong2*>(pp + ((size_t)(c0 + c) * NB + b) * ND + q * 4) = v;
    }
  }
}

// ---------------------------------------------------------------------------
// Routing pass: b_t=2, IN-WARP c-split. lane = half<<4 | bq<<2 | q.
// Global-max-first softmax: exchange max (1 shfl), exp once vs global M,
// exchange sum (1 shfl), one rcp — exact softmax, 12 MUFU/warp-n (was 16),
// shorter serial chain. Grid (144, 8).
// ---------------------------------------------------------------------------
__global__ void __launch_bounds__(128, 3)
route_kernel(const float* __restrict__ x, const float* __restrict__ W) {
  __shared__ float4 sW[2][STAGE_F4];
  __shared__ float4 sX[32 * XROW_R];
  const int chunk = blockIdx.x;
  const int n0 = chunk * NCHUNK_R;
  const int warp = threadIdx.x >> 5;
  const int lane = threadIdx.x & 31;
  const int half = lane >> 4;            // c-half
  const int bq = (lane >> 2) & 3;        // 0..3
  const int q  = lane & 3;               // d-quarter
  const int c0 = half * NCH;
  const int b_blk = blockIdx.y * 32;
  const int bl0 = warp * 8 + bq, bl1 = bl0 + 4;
  const int b0 = b_blk + bl0, b1 = b_blk + bl1;

  uint64_t S2[2][NCH][2];
#pragma unroll
  for (int bb = 0; bb < 2; bb++) {
    const int b = bb ? b1 : b0;
#pragma unroll
    for (int c = 0; c < NCH; c++) {
      const ulonglong2 v = *reinterpret_cast<const ulonglong2*>(
          g_S + ((size_t)(c0 + c) * NB + b) * ND + q * 4);
      S2[bb][c][0] = v.x; S2[bb][c][1] = v.y;
    }
  }
  uint64_t sp2[2][NCH][2];
#pragma unroll
  for (int bb = 0; bb < 2; bb++)
#pragma unroll
    for (int c = 0; c < NCH; c++) { sp2[bb][c][0] = pk2(0.f, 0.f); sp2[bb][c][1] = pk2(0.f, 0.f); }

  // x chunk: 32 rows x 32 f4 (16 n), padded 33.
  {
    const int t = threadIdx.x;
    const int r = t >> 2;
    const int j0 = (t & 3) * 8;
    const float4* src = reinterpret_cast<const float4*>(x) +
                        ((size_t)(b_blk + r) * NN + n0) * 2;
    const uint32_t base = (uint32_t)__cvta_generic_to_shared(sX + r * XROW_R);
#pragma unroll
    for (int j = 0; j < 8; j++)
      cpasync16(base + (j0 + j) * 16, src + j0 + j);
  }
  load_w_stage(sW[0], reinterpret_cast<const float4*>(W) + (size_t)n0 * WN_F4);
  asm volatile("cp.async.commit_group;");

#pragma unroll 1
  for (int s = 0; s < NCHUNK_R / STAGE_N; s++) {   // 4 stages
    if (s + 1 < NCHUNK_R / STAGE_N) {
      load_w_stage(sW[(s + 1) & 1],
                   reinterpret_cast<const float4*>(W) + (size_t)(n0 + (s + 1) * STAGE_N) * WN_F4);
      asm volatile("cp.async.commit_group;");
      asm volatile("cp.async.wait_group 1;");
    } else {
      asm volatile("cp.async.wait_group 0;");
    }
    __syncthreads();
    const float4* buf = sW[s & 1];
#pragma unroll
    for (int t = 0; t < STAGE_N; t++) {
      const int nn = s * STAGE_N + t;
      const float4 xa0 = sX[bl0 * XROW_R + nn * 2], xb0 = sX[bl0 * XROW_R + nn * 2 + 1];
      const float4 xa1 = sX[bl1 * XROW_R + nn * 2], xb1 = sX[bl1 * XROW_R + nn * 2 + 1];
      const float xr0[NI] = {xa0.x, xa0.y, xa0.z, xa0.w, xb0.x, xb0.y, xb0.z, xb0.w};
      const float xr1[NI] = {xa1.x, xa1.y, xa1.z, xa1.w, xb1.x, xb1.y, xb1.z, xb1.w};
      const float4* Wn = buf + t * WN_F4;

      uint64_t u2[2][NCH][2];
#pragma unroll
      for (int i = 0; i < NI; i++) {
        const uint64_t x20 = pk2(xr0[i], xr0[i]);
        const uint64_t x21 = pk2(xr1[i], xr1[i]);
#pragma unroll
        for (int c = 0; c < NCH; c++) {
          const ulonglong2 w = *reinterpret_cast<const ulonglong2*>(Wn + i * 40 + (c0 + c) * 4 + q);
          if (i == 0) {
            u2[0][c][0] = mul2(x20, w.x); u2[0][c][1] = mul2(x20, w.y);
            u2[1][c][0] = mul2(x21, w.x); u2[1][c][1] = mul2(x21, w.y);
          } else {
            fma2(u2[0][c][0], x20, w.x); fma2(u2[0][c][1], x20, w.y);
            fma2(u2[1][c][0], x21, w.x); fma2(u2[1][c][1], x21, w.y);
          }
        }
      }
      // logits: packed dot + cross-half add + q-lane reduction
      float lg[2][NCH];
#pragma unroll
      for (int bb = 0; bb < 2; bb++)
#pragma unroll
        for (int c = 0; c < NCH; c++) {
          uint64_t tt = mul2(u2[bb][c][0], S2[bb][c][0]);
          fma2(tt, u2[bb][c][1], S2[bb][c][1]);
          const float2 f = unpk(tt);
          float v = f.x + f.y;
          v += __shfl_xor_sync(0xffffffffu, v, 1);
          v += __shfl_xor_sync(0xffffffffu, v, 2);
          lg[bb][c] = v;
        }
      // softmax, global-max-first: M across halves, single exp set, one rcp
#pragma unroll
      for (int bb = 0; bb < 2; bb++) {
        float mm = lg[bb][0];
#pragma unroll
        for (int c = 1; c < NCH; c++) mm = fmaxf(mm, lg[bb][c]);
        const float M = fmaxf(mm, __shfl_xor_sync(0xffffffffu, mm, 16));
        float ss = 0.f;
#pragma unroll
        for (int c = 0; c < NCH; c++) { lg[bb][c] = __expf(lg[bb][c] - M); ss += lg[bb][c]; }
        const float tot = ss + __shfl_xor_sync(0xffffffffu, ss, 16);
        const float fac = __frcp_rn(tot);
#pragma unroll
        for (int c = 0; c < NCH; c++) {
          const float p = lg[bb][c] * fac;
          const uint64_t p2 = pk2(p, p);
          fma2(sp2[bb][c][0], p2, u2[bb][c][0]);
          fma2(sp2[bb][c][1], p2, u2[bb][c][1]);
        }
      }
    }
    __syncthreads();
  }
  float* pp = g_part + (size_t)chunk * (NB * NE);
#pragma unroll
  for (int bb = 0; bb < 2; bb++) {
    const int b = bb ? b1 : b0;
#pragma unroll
    for (int c = 0; c < NCH; c++) {
      ulonglong2 v; v.x = sp2[bb][c][0]; v.y = sp2[bb][c][1];
      *reinterpret_cast<ulonglong2*>(pp + ((size_t)(c0 + c) * NB + b) * ND + q * 4) = v;
    }
  }
}

// ---------------------------------------------------------------------------
// Reduction stage A: nchunks -> 4 group partials. Grid (160, 4).
// ---------------------------------------------------------------------------
__global__ void reduceA_kernel(int nchunks) {
  const int t = blockIdx.x * blockDim.x + threadIdx.x;
  const int g = blockIdx.y;
  const int per = nchunks >> 2;
  float sum = 0.f;
  const int k0 = g * per;
#pragma unroll 4
  for (int k = k0; k < k0 + per; k++)
    sum += g_part[(size_t)k * (NB * NE) + t];
  g_part2[(size_t)g * (NB * NE) + t] = sum;
}

// Reduction stage B: 4 -> 1 + bias + S_acc update / final squash.
__global__ void reduceB_kernel(int mode, float* __restrict__ out) {
  const int t = blockIdx.x * blockDim.x + threadIdx.x;
  float sum = 0.f;
#pragma unroll
  for (int g = 0; g < NGROUP; g++) sum += g_part2[(size_t)g * (NB * NE) + t];

  if (mode == 0) {
    g_S[t] = 0.1f * sum + 0.1f;
  } else if (mode == 1) {
    g_S[t] = g_S[t] + sum + 0.1f;
  } else {
    const float s = sum + 0.1f;
    float nsq = s * s;
    nsq += __shfl_xor_sync(0xffffffffu, nsq, 1);
    nsq += __shfl_xor_sync(0xffffffffu, nsq, 2);
    nsq += __shfl_xor_sync(0xffffffffu, nsq, 4);
    nsq += __shfl_xor_sync(0xffffffffu, nsq, 8);
    const float nrm = sqrtf(nsq);
    const float v = s * nrm / (1.f + nsq);
    const int d = t & 15;
    const int b = (t >> 4) & 255;
    const int c = t >> 12;
    out[((size_t)b * NCLS + c) * ND + d] = v;
  }
}

extern "C" void kernel_launch(void* const* d_in, const int* in_sizes, int n_in,
                              void* d_out, int out_size) {
  const float* x = (const float*)d_in[0];   // [256, 2304, 8] f32
  const float* W = (const float*)d_in[1];   // [2304, 8, 160] f32
  float* out = (float*)d_out;               // [256, 10, 16] f32

  const dim3 pgrid(NUM_CHUNKS_P, 4);        // produce: 64 b per block
  const dim3 rgrid(NUM_CHUNKS_R, 8);        // route: 32 b per block
  const dim3 rgridA(160, NGROUP);

  produce_kernel<<<pgrid, 128>>>(x, W);
  reduceA_kernel<<<rgridA, 256>>>(NUM_CHUNKS_P);
  reduceB_kernel<<<160, 256>>>(0, out);    // g_S = s0
  route_kernel<<<rgrid, 128>>>(x, W);
  reduceA_kernel<<<rgridA, 256>>>(NUM_CHUNKS_R);
  reduceB_kernel<<<160, 256>>>(1, out);    // g_S = s0 + s1
  route_kernel<<<rgrid, 128>>>(x, W);
  reduceA_kernel<<<rgridA, 256>>>(NUM_CHUNKS_R);
  reduceB_kernel<<<160, 256>>>(2, out);    // final + squash
}